// round 16
// baseline (speedup 1.0000x reference)
#include <cuda_runtime.h>
#include <cuda_bf16.h>

// out[n,c] = 0.05f * sum_{m,t,v} x[n,m,c,t,v]
//
// The reference's 3-level VQ (cosine-sim argmax) + segment_sum pipeline
// conserves per-sample totals at every pooling level (every row always maps
// to exactly one in-sample segment), so the output is independent of the
// prototypes: per-(n,c) sum scaled by (1/M)*(1/Kl) = (1/2)*(1/10) = 0.05.
//
// FINAL: block-per-output, 320 threads (1600 float4 per m-slice / 320 = 5
// exact -> fully unrolled, branch-free, 10 independent L2-only (__ldcg)
// float4 loads in flight per thread), warp+block shuffle reduce.
//
// At the machine roofline: 6.8-7.0 TB/s (85-88% of HBM3e spec) = the B300
// full-chip LTS cap (~6300 B/cyc, path-independent) at sustained clock, and
// within 2.5% of the 419MB information floor at the chip's best observed
// rate. EIGHT benches of this exact source: mean 61.7us, sigma ~0.3us,
// range 61.4-62.2 -> residual is DVFS clock variance, not structure.
// Measured-neutral alternatives: warp-per-output (-), persistent grid (0),
// halved concurrent stream count (0), __ldcs/__ldcg/default (0), 256-thread
// blocks (-). Latency hiding >30x margin; compute pipes <11%. Ledger closed.

#define N_SAMP 32
#define M_DIM  2
#define C_DIM  256
#define TV     6400          // T*V = 256*25
#define TV4    1600          // TV / 4
#define BT     320           // 1600 / 320 = 5 exactly

__global__ __launch_bounds__(BT)
void pretrain_neck_reduce(const float* __restrict__ x, float* __restrict__ out) {
    const int bid = blockIdx.x;            // [0, N_SAMP*C_DIM)
    const int n = bid >> 8;
    const int c = bid & 255;

    const int tid = threadIdx.x;

    const float4* p0 = reinterpret_cast<const float4*>(
        x + ((size_t)(n * M_DIM + 0) * C_DIM + c) * (size_t)TV);
    const float4* p1 = reinterpret_cast<const float4*>(
        x + ((size_t)(n * M_DIM + 1) * C_DIM + c) * (size_t)TV);

    // 10 independent L2-only loads, fully unrolled — no tail, no predication.
    float4 v[10];
    #pragma unroll
    for (int j = 0; j < 5; ++j) {
        v[j]     = __ldcg(p0 + tid + j * BT);
        v[j + 5] = __ldcg(p1 + tid + j * BT);
    }

    float s0 = 0.f, s1 = 0.f;
    #pragma unroll
    for (int j = 0; j < 5; ++j) {
        s0 += (v[j].x + v[j].y) + (v[j].z + v[j].w);
        s1 += (v[j + 5].x + v[j + 5].y) + (v[j + 5].z + v[j + 5].w);
    }
    float s = s0 + s1;

    // warp reduce
    #pragma unroll
    for (int off = 16; off > 0; off >>= 1)
        s += __shfl_down_sync(0xFFFFFFFFu, s, off);

    __shared__ float warp_sums[10];
    const int lane = tid & 31;
    const int wid  = tid >> 5;
    if (lane == 0) warp_sums[wid] = s;
    __syncthreads();

    if (wid == 0) {
        float t = (lane < 10) ? warp_sums[lane] : 0.f;
        #pragma unroll
        for (int off = 8; off > 0; off >>= 1)
            t += __shfl_down_sync(0xFFFFFFFFu, t, off);
        if (lane == 0)
            out[bid] = t * 0.05f;   // (1/M) * (1/Kl) = (1/2)*(1/10)
    }
}

extern "C" void kernel_launch(void* const* d_in, const int* in_sizes, int n_in,
                              void* d_out, int out_size) {
    const float* x = (const float*)d_in[0];   // [N, M, C, T, V] fp32
    float* out = (float*)d_out;               // [N, C] fp32
    (void)in_sizes; (void)n_in; (void)out_size;
    pretrain_neck_reduce<<<N_SAMP * C_DIM, BT>>>(x, out);
}

// round 17
// speedup vs baseline: 1.0083x; 1.0083x over previous
#include <cuda_runtime.h>
#include <cuda_bf16.h>

// out[n,c] = 0.05f * sum_{m,t,v} x[n,m,c,t,v]
//
// The reference's 3-level VQ (cosine-sim argmax) + segment_sum pipeline
// conserves per-sample totals at every pooling level (every row always maps
// to exactly one in-sample segment), so the output is independent of the
// prototypes: per-(n,c) sum scaled by (1/M)*(1/Kl) = (1/2)*(1/10) = 0.05.
//
// FINAL: block-per-output, 320 threads (1600 float4 per m-slice / 320 = 5
// exact -> fully unrolled, branch-free, 10 independent L2-only (__ldcg)
// float4 loads in flight per thread), warp+block shuffle reduce.
//
// At the machine roofline: 6.8-7.0 TB/s (85-88% of HBM3e spec) = the B300
// full-chip LTS cap (~6300 B/cyc, path-independent) at sustained clock, and
// within 2.5% of the 419MB information floor at the chip's best observed
// rate. NINE benches of this exact source: mean 61.75us, sigma ~0.3us,
// range 61.4-62.2 -> residual is DVFS clock variance, not structure.
// Measured-neutral alternatives: warp-per-output (-), persistent grid (0),
// halved concurrent stream count (0), __ldcs/__ldcg/default (0), 256-thread
// blocks (-). Latency hiding >30x margin; compute pipes <11%. Ledger closed.

#define N_SAMP 32
#define M_DIM  2
#define C_DIM  256
#define TV     6400          // T*V = 256*25
#define TV4    1600          // TV / 4
#define BT     320           // 1600 / 320 = 5 exactly

__global__ __launch_bounds__(BT)
void pretrain_neck_reduce(const float* __restrict__ x, float* __restrict__ out) {
    const int bid = blockIdx.x;            // [0, N_SAMP*C_DIM)
    const int n = bid >> 8;
    const int c = bid & 255;

    const int tid = threadIdx.x;

    const float4* p0 = reinterpret_cast<const float4*>(
        x + ((size_t)(n * M_DIM + 0) * C_DIM + c) * (size_t)TV);
    const float4* p1 = reinterpret_cast<const float4*>(
        x + ((size_t)(n * M_DIM + 1) * C_DIM + c) * (size_t)TV);

    // 10 independent L2-only loads, fully unrolled — no tail, no predication.
    float4 v[10];
    #pragma unroll
    for (int j = 0; j < 5; ++j) {
        v[j]     = __ldcg(p0 + tid + j * BT);
        v[j + 5] = __ldcg(p1 + tid + j * BT);
    }

    float s0 = 0.f, s1 = 0.f;
    #pragma unroll
    for (int j = 0; j < 5; ++j) {
        s0 += (v[j].x + v[j].y) + (v[j].z + v[j].w);
        s1 += (v[j + 5].x + v[j + 5].y) + (v[j + 5].z + v[j + 5].w);
    }
    float s = s0 + s1;

    // warp reduce
    #pragma unroll
    for (int off = 16; off > 0; off >>= 1)
        s += __shfl_down_sync(0xFFFFFFFFu, s, off);

    __shared__ float warp_sums[10];
    const int lane = tid & 31;
    const int wid  = tid >> 5;
    if (lane == 0) warp_sums[wid] = s;
    __syncthreads();

    if (wid == 0) {
        float t = (lane < 10) ? warp_sums[lane] : 0.f;
        #pragma unroll
        for (int off = 8; off > 0; off >>= 1)
            t += __shfl_down_sync(0xFFFFFFFFu, t, off);
        if (lane == 0)
            out[bid] = t * 0.05f;   // (1/M) * (1/Kl) = (1/2)*(1/10)
    }
}

extern "C" void kernel_launch(void* const* d_in, const int* in_sizes, int n_in,
                              void* d_out, int out_size) {
    const float* x = (const float*)d_in[0];   // [N, M, C, T, V] fp32
    float* out = (float*)d_out;               // [N, C] fp32
    (void)in_sizes; (void)n_in; (void)out_size;
    pretrain_neck_reduce<<<N_SAMP * C_DIM, BT>>>(x, out);
}